// round 15
// baseline (speedup 1.0000x reference)
#include <cuda_runtime.h>
#include <cuda_fp16.h>
#include <stdint.h>

// Problem constants
#define BB 2
#define NN 16384
#define KK 32
#define FF 64
#define EE 16
#define NT (BB * NN)      // 32768 nodes
#define SK (FF * EE)      // 1024 = GEMM contraction length

// Scratch (static __device__ arrays — no runtime allocation)
__device__ __align__(32) __half g_S[(size_t)NT * SK];   // 64 MB: S (fp16)
__device__ __align__(16) __half g_B[FF * SK];           // B[n][k] = w2^T (fp16)
__device__ __align__(16) __half g_Gh[(size_t)NT * FF];  // 4 MB: nodes in fp16

static __device__ __forceinline__ uint32_t hfpack(float hi, float lo) {
    uint32_t r;
    asm("cvt.rn.f16x2.f32 %0, %1, %2;" : "=r"(r) : "f"(hi), "f"(lo));
    return r;
}
static __device__ __forceinline__ uint32_t smem_u32(const void* p) {
    uint32_t a;
    asm("{ .reg .u64 t; cvta.to.shared.u64 t, %1; cvt.u32.u64 %0, t; }" : "=r"(a) : "l"(p));
    return a;
}
static __device__ __forceinline__ void ldsm4(uint32_t* r, uint32_t addr) {
    asm volatile("ldmatrix.sync.aligned.m8n8.x4.shared.b16 {%0,%1,%2,%3}, [%4];"
                 : "=r"(r[0]), "=r"(r[1]), "=r"(r[2]), "=r"(r[3]) : "r"(addr));
}
static __device__ __forceinline__ void ldsm4t(uint32_t* r, uint32_t addr) {
    asm volatile("ldmatrix.sync.aligned.m8n8.x4.trans.shared.b16 {%0,%1,%2,%3}, [%4];"
                 : "=r"(r[0]), "=r"(r[1]), "=r"(r[2]), "=r"(r[3]) : "r"(addr));
}
static __device__ __forceinline__ void mma16816h(float* c, const uint32_t* a,
                                                 const uint32_t* b) {
    asm volatile(
        "mma.sync.aligned.m16n8k16.row.col.f32.f16.f16.f32 "
        "{%0,%1,%2,%3}, {%4,%5,%6,%7}, {%8,%9}, {%0,%1,%2,%3};"
        : "+f"(c[0]), "+f"(c[1]), "+f"(c[2]), "+f"(c[3])
        : "r"(a[0]), "r"(a[1]), "r"(a[2]), "r"(a[3]), "r"(b[0]), "r"(b[1]));
}
static __device__ __forceinline__ void cpa16(uint32_t dst, const void* src) {
    asm volatile("cp.async.cg.shared.global [%0], [%1], 16;"
                 :: "r"(dst), "l"(src) : "memory");
}
#define CP_COMMIT() asm volatile("cp.async.commit_group;" ::: "memory")
#define CP_WAIT(n)  asm volatile("cp.async.wait_group %0;" :: "n"(n) : "memory")

// 256-bit evict-policy accesses (ptxas requires .v4.b64 for L2::evict_*)
static __device__ __forceinline__ void ldg_ef32(const float* p,
                                                float4& a, float4& b) {
    unsigned long long r0, r1, r2, r3;
    asm volatile("ld.global.L2::evict_first.v4.b64 {%0,%1,%2,%3}, [%4];"
                 : "=l"(r0), "=l"(r1), "=l"(r2), "=l"(r3) : "l"(p));
    a.x = __uint_as_float((uint32_t)r0);  a.y = __uint_as_float((uint32_t)(r0 >> 32));
    a.z = __uint_as_float((uint32_t)r1);  a.w = __uint_as_float((uint32_t)(r1 >> 32));
    b.x = __uint_as_float((uint32_t)r2);  b.y = __uint_as_float((uint32_t)(r2 >> 32));
    b.z = __uint_as_float((uint32_t)r3);  b.w = __uint_as_float((uint32_t)(r3 >> 32));
}
static __device__ __forceinline__ void stg_el32(void* p, uint4 a, uint4 b) {
    unsigned long long r0 = (unsigned long long)a.x | ((unsigned long long)a.y << 32);
    unsigned long long r1 = (unsigned long long)a.z | ((unsigned long long)a.w << 32);
    unsigned long long r2 = (unsigned long long)b.x | ((unsigned long long)b.y << 32);
    unsigned long long r3 = (unsigned long long)b.z | ((unsigned long long)b.w << 32);
    asm volatile("st.global.L2::evict_last.v4.b64 [%0], {%1,%2,%3,%4};"
                 :: "l"(p), "l"(r0), "l"(r1), "l"(r2), "l"(r3) : "memory");
}

// ---- kernel 0: nodes -> fp16 (g_Gh) + W2 transpose -> g_B (fp16) ----
__global__ __launch_bounds__(256) void k_conv(
    const float* __restrict__ nodes, const float* __restrict__ w)
{
    int t = blockIdx.x * 256 + threadIdx.x;          // 0 .. 524287
    float4 v = reinterpret_cast<const float4*>(nodes)[t];
    reinterpret_cast<uint2*>(g_Gh)[t] =
        make_uint2(hfpack(v.y, v.x), hfpack(v.w, v.z));
    if (t < FF * SK) {                               // id = n*1024 + k
        int n = t >> 10;
        int k = t & 1023;
        int l = k >> 4;
        int e = k & 15;
        g_B[t] = __float2half(w[l * (FF * EE) + n * EE + e]);
    }
}

// ---- kernel 1 (tensor): per node, S[64l][16n] = sum_j G[j][l] * (E[j][n]/32) ----
// One warp per node; E (DRAM, 32B evict_first) before G (L2) gather for MLP.
// S stores 32B evict_last -> stage2 reads S from L2, not DRAM.
#define S1NODES 8
#define GP 144                    // G row pitch bytes
#define EP 48                     // E row pitch bytes
#define GBYTES (32 * GP)          // 4608
#define EBYTES (32 * EP)          // 1536
#define NODE_SM (GBYTES + EBYTES)           // 6144
#define S1SMEM (S1NODES * NODE_SM)          // 49152

__global__ __launch_bounds__(256) void k_stage1(
    const int*   __restrict__ nlist,
    const float* __restrict__ edges)
{
    extern __shared__ __align__(16) char sm1[];
    const int t    = threadIdx.x;
    const int warp = t >> 5;
    const int lane = t & 31;
    const int g    = blockIdx.x * S1NODES + warp;
    const int b    = g >> 14;

    char* base = sm1 + warp * NODE_SM;
    const uint32_t sb = smem_u32(base);

    const int my_idx = nlist[(size_t)g * KK + lane];
    const __half* nbase = g_Gh + (size_t)b * (NN * FF);
    const int l4   = lane & 7;
    const int rsub = lane >> 3;

    // E loads first (DRAM, longest latency; 2 x 32B evict_first per lane)
    float4 ev[4];
    {
        const float* efp = edges + (size_t)g * 512;
        ldg_ef32(efp + (lane)      * 8, ev[0], ev[1]);   // float4 ids 2*lane, +1
        ldg_ef32(efp + (32 + lane) * 8, ev[2], ev[3]);   // float4 ids 64+2*lane, +1
    }
    uint4 gv[8];
#pragma unroll
    for (int p = 0; p < 8; p++) {
        int j = p * 4 + rsub;
        int jdx = __shfl_sync(0xffffffffu, my_idx, j);
        gv[p] = *reinterpret_cast<const uint4*>(nbase + (size_t)jdx * FF + l4 * 8);
    }
#pragma unroll
    for (int p = 0; p < 8; p++)
        *reinterpret_cast<uint4*>(base + (p * 4 + rsub) * GP + l4 * 16) = gv[p];
    // E -> smem: chunk qq covers float4 ids u = qq*64 + 2*lane (+1)
#pragma unroll
    for (int qq = 0; qq < 2; qq++) {
#pragma unroll
        for (int h = 0; h < 2; h++) {
            int u = qq * 64 + 2 * lane + h;              // float4 id 0..127
            const float4 v = ev[qq * 2 + h];
            int j = u >> 2, n4 = u & 3;
            *reinterpret_cast<uint2*>(base + GBYTES + j * EP + n4 * 8) =
                make_uint2(hfpack(v.y * 0.03125f, v.x * 0.03125f),
                           hfpack(v.w * 0.03125f, v.z * 0.03125f));
        }
    }
    __syncwarp();

    // ldmatrix.trans fragment addresses (proven mappings)
    const uint32_t aA = sb + ((lane & 7) + 8 * (lane >> 4)) * GP
                           + ((lane >> 3) & 1) * 16;
    const uint32_t aB = sb + GBYTES
                           + ((lane & 7) + 8 * ((lane >> 3) & 1)) * EP
                           + (lane >> 4) * 16;

    float C[4][2][4];
#pragma unroll
    for (int mt = 0; mt < 4; mt++)
#pragma unroll
        for (int nt = 0; nt < 2; nt++)
#pragma unroll
            for (int i = 0; i < 4; i++) C[mt][nt][i] = 0.0f;

#pragma unroll
    for (int ks = 0; ks < 2; ks++) {
        uint32_t bh[4];
        ldsm4t(bh, aB + ks * 16 * EP);
#pragma unroll
        for (int mt = 0; mt < 4; mt++) {
            uint32_t ah[4];
            ldsm4t(ah, aA + ks * 16 * GP + mt * 32);
            mma16816h(C[mt][0], ah, bh);
            mma16816h(C[mt][1], ah, bh + 2);
        }
    }

    // epilogue: pack fp16, stage in smem, 2 x 32B evict_last stores per lane
    __syncwarp();
    __half* sstage = reinterpret_cast<__half*>(base);
    const int r = lane >> 2, q = lane & 3;
#pragma unroll
    for (int mt = 0; mt < 4; mt++) {
#pragma unroll
        for (int nt = 0; nt < 2; nt++) {
            int k0 = (mt * 16 + r) * 16 + nt * 8 + 2 * q;       // (c0,c1)
            *reinterpret_cast<uint32_t*>(sstage + k0) =
                hfpack(C[mt][nt][1], C[mt][nt][0]);
            *reinterpret_cast<uint32_t*>(sstage + k0 + 128) =
                hfpack(C[mt][nt][3], C[mt][nt][2]);
        }
    }
    __syncwarp();
    {
        char* dst = reinterpret_cast<char*>(g_S + (size_t)g * SK);
        const uint4* src = reinterpret_cast<const uint4*>(sstage);
#pragma unroll
        for (int i = 0; i < 2; i++) {
            int j = i * 32 + lane;                       // 32B unit 0..63
            stg_el32(dst + j * 32, src[2 * j], src[2 * j + 1]);
        }
    }
}

// ---- kernel 2: HMMA GEMM out[32768 x 64] = S(fp16) @ W2(fp16) ----
// M-tile 128, grid 256. cp.async double-buffered A+B staging.
#define KC 64
#define PIT 144
#define SA0 0
#define SA1 (128 * PIT)                      // 18432
#define SB0 (2 * 128 * PIT)                  // 36864
#define SB1 (SB0 + 64 * PIT)                 // 46080
#define SMEM2_SZ (SB1 + 64 * PIT)            // 55296

__global__ __launch_bounds__(256) void k_stage2(float* __restrict__ out)
{
    extern __shared__ __align__(16) char sm[];
    const int t    = threadIdx.x;
    const int w    = t >> 5;
    const int lane = t & 31;
    const int wr   = w & 3;                  // row group (32 rows)
    const int wc   = w >> 2;                 // col group (32 cols)
    const int m0   = blockIdx.x * 128;
    const uint32_t smb = smem_u32(sm);

    const int ar = t >> 3;                   // 0..31
    const int aj = t & 7;

    const int a_r = (lane & 7) + ((lane >> 3) & 1) * 8;
    const int a_k = (lane >> 4) * 8;
    const uint32_t aAoff = (uint32_t)(wr * 32 + a_r) * PIT + a_k * 2;
    const uint32_t aBoff = (uint32_t)(wc * 32 + 8 * (lane >> 4) + (lane & 7)) * PIT
                         + ((lane >> 3) & 1) * 16;

    auto issue = [&](int c) {
        const int kk = c * KC;
        const uint32_t bufA = smb + ((c & 1) ? SA1 : SA0);
        const uint32_t bufB = smb + ((c & 1) ? SB1 : SB0);
#pragma unroll
        for (int qq = 0; qq < 4; qq++) {
            int row = ar + 32 * qq;
            cpa16(bufA + row * PIT + aj * 16,
                  g_S + (size_t)(m0 + row) * SK + kk + aj * 8);
        }
#pragma unroll
        for (int q2 = 0; q2 < 2; q2++) {
            int u = t + q2 * 256;            // 0..511
            int n = u >> 3, j = u & 7;
            cpa16(bufB + n * PIT + j * 16, g_B + (size_t)n * SK + kk + j * 8);
        }
        CP_COMMIT();
    };

    float acc[2][4][4];
#pragma unroll
    for (int s = 0; s < 2; s++)
#pragma unroll
        for (int nt = 0; nt < 4; nt++)
#pragma unroll
            for (int i = 0; i < 4; i++) acc[s][nt][i] = 0.0f;

    issue(0);
    for (int c = 0; c < SK / KC; c++) {      // 16 chunks
        if (c < 15) { issue(c + 1); CP_WAIT(1); }
        else        { CP_WAIT(0); }
        __syncthreads();

        const uint32_t bufA = smb + ((c & 1) ? SA1 : SA0);
        const uint32_t bufB = smb + ((c & 1) ? SB1 : SB0);
#pragma unroll
        for (int ks = 0; ks < 4; ks++) {
            const int kb2 = ks * 32;
            uint32_t a0[4], a1[4];
            ldsm4(a0, bufA + aAoff + kb2);
            ldsm4(a1, bufA + aAoff + 16 * PIT + kb2);
            uint32_t bf[4][2];
#pragma unroll
            for (int p = 0; p < 2; p++) {
                uint32_t r4[4];
                ldsm4(r4, bufB + aBoff + p * 16 * PIT + kb2);
                bf[2 * p][0] = r4[0]; bf[2 * p][1] = r4[1];
                bf[2 * p + 1][0] = r4[2]; bf[2 * p + 1][1] = r4[3];
            }
#pragma unroll
            for (int nt = 0; nt < 4; nt++) {
                mma16816h(acc[0][nt], a0, bf[nt]);
                mma16816h(acc[1][nt], a1, bf[nt]);
            }
        }
        __syncthreads();                     // buffer reuse guard
    }

    // epilogue
    const int cb = 2 * (lane & 3);
#pragma unroll
    for (int s = 0; s < 2; s++) {
        const int row0 = m0 + wr * 32 + s * 16 + (lane >> 2);
#pragma unroll
        for (int nt = 0; nt < 4; nt++) {
            int col = (wc * 4 + nt) * 8 + cb;
            *reinterpret_cast<float2*>(out + (size_t)row0 * FF + col) =
                make_float2(acc[s][nt][0], acc[s][nt][1]);
            *reinterpret_cast<float2*>(out + (size_t)(row0 + 8) * FF + col) =
                make_float2(acc[s][nt][2], acc[s][nt][3]);
        }
    }
}

extern "C" void kernel_launch(void* const* d_in, const int* in_sizes, int n_in,
                              void* d_out, int out_size) {
    const float* nodes = (const float*)d_in[0];
    const int*   nlist = (const int*)d_in[1];
    const float* edges = (const float*)d_in[2];
    const float* w     = (const float*)d_in[3];
    float* out = (float*)d_out;
    (void)in_sizes; (void)n_in; (void)out_size;

    cudaFuncSetAttribute(k_stage1,
                         cudaFuncAttributeMaxDynamicSharedMemorySize, S1SMEM);
    cudaFuncSetAttribute(k_stage2,
                         cudaFuncAttributeMaxDynamicSharedMemorySize, SMEM2_SZ);

    k_conv<<<NT * FF / 4 / 256, 256>>>(nodes, w);
    k_stage1<<<NT / S1NODES, 256, S1SMEM>>>(nlist, edges);
    k_stage2<<<NT / 128, 256, SMEM2_SZ>>>(out);
}

// round 16
// speedup vs baseline: 1.1063x; 1.1063x over previous
#include <cuda_runtime.h>
#include <cuda_fp16.h>
#include <stdint.h>

// Problem constants
#define BB 2
#define NN 16384
#define KK 32
#define FF 64
#define EE 16
#define NT (BB * NN)      // 32768 nodes
#define SK (FF * EE)      // 1024 = GEMM contraction length

// Scratch (static __device__ arrays — no runtime allocation)
__device__ __align__(16) __half g_S[(size_t)NT * SK];   // 64 MB: S (fp16)
__device__ __align__(16) __half g_B[FF * SK];           // B[n][k] = w2^T (fp16)
__device__ __align__(16) __half g_Gh[(size_t)NT * FF];  // 4 MB: nodes in fp16

static __device__ __forceinline__ uint32_t hfpack(float hi, float lo) {
    uint32_t r;
    asm("cvt.rn.f16x2.f32 %0, %1, %2;" : "=r"(r) : "f"(hi), "f"(lo));
    return r;
}
static __device__ __forceinline__ uint32_t smem_u32(const void* p) {
    uint32_t a;
    asm("{ .reg .u64 t; cvta.to.shared.u64 t, %1; cvt.u32.u64 %0, t; }" : "=r"(a) : "l"(p));
    return a;
}
static __device__ __forceinline__ void ldsm4(uint32_t* r, uint32_t addr) {
    asm volatile("ldmatrix.sync.aligned.m8n8.x4.shared.b16 {%0,%1,%2,%3}, [%4];"
                 : "=r"(r[0]), "=r"(r[1]), "=r"(r[2]), "=r"(r[3]) : "r"(addr));
}
static __device__ __forceinline__ void ldsm4t(uint32_t* r, uint32_t addr) {
    asm volatile("ldmatrix.sync.aligned.m8n8.x4.trans.shared.b16 {%0,%1,%2,%3}, [%4];"
                 : "=r"(r[0]), "=r"(r[1]), "=r"(r[2]), "=r"(r[3]) : "r"(addr));
}
static __device__ __forceinline__ void mma16816h(float* c, const uint32_t* a,
                                                 const uint32_t* b) {
    asm volatile(
        "mma.sync.aligned.m16n8k16.row.col.f32.f16.f16.f32 "
        "{%0,%1,%2,%3}, {%4,%5,%6,%7}, {%8,%9}, {%0,%1,%2,%3};"
        : "+f"(c[0]), "+f"(c[1]), "+f"(c[2]), "+f"(c[3])
        : "r"(a[0]), "r"(a[1]), "r"(a[2]), "r"(a[3]), "r"(b[0]), "r"(b[1]));
}
static __device__ __forceinline__ void cpa16(uint32_t dst, const void* src) {
    asm volatile("cp.async.cg.shared.global [%0], [%1], 16;"
                 :: "r"(dst), "l"(src) : "memory");
}
#define CP_COMMIT() asm volatile("cp.async.commit_group;" ::: "memory")
#define CP_WAIT(n)  asm volatile("cp.async.wait_group %0;" :: "n"(n) : "memory")

// ---- kernel 0: nodes -> fp16 (g_Gh) + W2 transpose -> g_B (fp16) ----
__global__ __launch_bounds__(256) void k_conv(
    const float* __restrict__ nodes, const float* __restrict__ w)
{
    int t = blockIdx.x * 256 + threadIdx.x;          // 0 .. 524287
    float4 v = reinterpret_cast<const float4*>(nodes)[t];
    reinterpret_cast<uint2*>(g_Gh)[t] =
        make_uint2(hfpack(v.y, v.x), hfpack(v.w, v.z));
    if (t < FF * SK) {                               // id = n*1024 + k
        int n = t >> 10;
        int k = t & 1023;
        int l = k >> 4;
        int e = k & 15;
        g_B[t] = __float2half(w[l * (FF * EE) + n * EE + e]);
    }
}

// ---- kernel 1 (tensor): per node, S[64l][16n] = sum_j G[j][l] * (E[j][n]/32) ----
// One warp per node; E (DRAM) loads issued before G (L2) gather for max MLP.
#define S1NODES 8
#define GP 144                    // G row pitch bytes
#define EP 48                     // E row pitch bytes
#define GBYTES (32 * GP)          // 4608
#define EBYTES (32 * EP)          // 1536
#define NODE_SM (GBYTES + EBYTES)           // 6144
#define S1SMEM (S1NODES * NODE_SM)          // 49152

__global__ __launch_bounds__(256) void k_stage1(
    const int*   __restrict__ nlist,
    const float* __restrict__ edges)
{
    extern __shared__ __align__(16) char sm1[];
    const int t    = threadIdx.x;
    const int warp = t >> 5;
    const int lane = t & 31;
    const int g    = blockIdx.x * S1NODES + warp;
    const int b    = g >> 14;

    char* base = sm1 + warp * NODE_SM;
    const uint32_t sb = smem_u32(base);

    const int my_idx = nlist[(size_t)g * KK + lane];
    const __half* nbase = g_Gh + (size_t)b * (NN * FF);
    const int l4   = lane & 7;
    const int rsub = lane >> 3;

    // E loads first (DRAM, longest latency), then gather (L2): 12 outstanding
    float4 ev[4];
    {
        const float4* ef = reinterpret_cast<const float4*>(edges) + (size_t)g * 128;
#pragma unroll
        for (int qq = 0; qq < 4; qq++) ev[qq] = ef[qq * 32 + lane];
    }
    uint4 gv[8];
#pragma unroll
    for (int p = 0; p < 8; p++) {
        int j = p * 4 + rsub;
        int jdx = __shfl_sync(0xffffffffu, my_idx, j);
        gv[p] = *reinterpret_cast<const uint4*>(nbase + (size_t)jdx * FF + l4 * 8);
    }
#pragma unroll
    for (int p = 0; p < 8; p++)
        *reinterpret_cast<uint4*>(base + (p * 4 + rsub) * GP + l4 * 16) = gv[p];
#pragma unroll
    for (int qq = 0; qq < 4; qq++) {
        int u = qq * 32 + lane;
        int j = u >> 2, n4 = u & 3;
        *reinterpret_cast<uint2*>(base + GBYTES + j * EP + n4 * 8) =
            make_uint2(hfpack(ev[qq].y * 0.03125f, ev[qq].x * 0.03125f),
                       hfpack(ev[qq].w * 0.03125f, ev[qq].z * 0.03125f));
    }
    __syncwarp();

    // ldmatrix.trans fragment addresses (proven mappings)
    const uint32_t aA = sb + ((lane & 7) + 8 * (lane >> 4)) * GP
                           + ((lane >> 3) & 1) * 16;
    const uint32_t aB = sb + GBYTES
                           + ((lane & 7) + 8 * ((lane >> 3) & 1)) * EP
                           + (lane >> 4) * 16;

    float C[4][2][4];
#pragma unroll
    for (int mt = 0; mt < 4; mt++)
#pragma unroll
        for (int nt = 0; nt < 2; nt++)
#pragma unroll
            for (int i = 0; i < 4; i++) C[mt][nt][i] = 0.0f;

#pragma unroll
    for (int ks = 0; ks < 2; ks++) {
        uint32_t bh[4];
        ldsm4t(bh, aB + ks * 16 * EP);
#pragma unroll
        for (int mt = 0; mt < 4; mt++) {
            uint32_t ah[4];
            ldsm4t(ah, aA + ks * 16 * GP + mt * 32);
            mma16816h(C[mt][0], ah, bh);
            mma16816h(C[mt][1], ah, bh + 2);
        }
    }

    // epilogue: pack fp16, stage in smem (reuse G region), coalesced STG.128
    __syncwarp();
    __half* sstage = reinterpret_cast<__half*>(base);
    const int r = lane >> 2, q = lane & 3;
#pragma unroll
    for (int mt = 0; mt < 4; mt++) {
#pragma unroll
        for (int nt = 0; nt < 2; nt++) {
            int k0 = (mt * 16 + r) * 16 + nt * 8 + 2 * q;       // (c0,c1)
            *reinterpret_cast<uint32_t*>(sstage + k0) =
                hfpack(C[mt][nt][1], C[mt][nt][0]);
            *reinterpret_cast<uint32_t*>(sstage + k0 + 128) =
                hfpack(C[mt][nt][3], C[mt][nt][2]);
        }
    }
    __syncwarp();
    {
        uint4* dst = reinterpret_cast<uint4*>(g_S + (size_t)g * SK);
        const uint4* src = reinterpret_cast<const uint4*>(sstage);
#pragma unroll
        for (int u = 0; u < 4; u++)
            dst[u * 32 + lane] = src[u * 32 + lane];
    }
}

// ---- kernel 2: HMMA GEMM out[32768 x 64] = S(fp16) @ W2(fp16) ----
// M-tile 128, grid 256. TRIPLE-buffered cp.async pipeline, ONE sync per chunk:
// issue(c+2) targets the buffer compute(c-1) used, whose readers are already
// past this iteration's barrier. 2 chunks of copy in flight (wait_group 1).
#define KC 64
#define PIT 144
#define ABUF (128 * PIT)                     // 18432
#define BBUFB (64 * PIT)                     // 9216
#define SB_BASE (3 * ABUF)                   // 55296
#define SMEM2_SZ (SB_BASE + 3 * BBUFB)       // 82944

__global__ __launch_bounds__(256) void k_stage2(float* __restrict__ out)
{
    extern __shared__ __align__(16) char sm[];
    const int t    = threadIdx.x;
    const int w    = t >> 5;
    const int lane = t & 31;
    const int wr   = w & 3;                  // row group (32 rows)
    const int wc   = w >> 2;                 // col group (32 cols)
    const int m0   = blockIdx.x * 128;
    const uint32_t smb = smem_u32(sm);

    const int ar = t >> 3;                   // 0..31
    const int aj = t & 7;

    const int a_r = (lane & 7) + ((lane >> 3) & 1) * 8;
    const int a_k = (lane >> 4) * 8;
    const uint32_t aAoff = (uint32_t)(wr * 32 + a_r) * PIT + a_k * 2;
    const uint32_t aBoff = (uint32_t)(wc * 32 + 8 * (lane >> 4) + (lane & 7)) * PIT
                         + ((lane >> 3) & 1) * 16;

    auto issue = [&](int c) {
        const int kk  = c * KC;
        const int s3  = c % 3;
        const uint32_t bufA = smb + s3 * ABUF;
        const uint32_t bufB = smb + SB_BASE + s3 * BBUFB;
#pragma unroll
        for (int qq = 0; qq < 4; qq++) {
            int row = ar + 32 * qq;
            cpa16(bufA + row * PIT + aj * 16,
                  g_S + (size_t)(m0 + row) * SK + kk + aj * 8);
        }
#pragma unroll
        for (int q2 = 0; q2 < 2; q2++) {
            int u = t + q2 * 256;            // 0..511
            int n = u >> 3, j = u & 7;
            cpa16(bufB + n * PIT + j * 16, g_B + (size_t)n * SK + kk + j * 8);
        }
        CP_COMMIT();
    };

    float acc[2][4][4];
#pragma unroll
    for (int s = 0; s < 2; s++)
#pragma unroll
        for (int nt = 0; nt < 4; nt++)
#pragma unroll
            for (int i = 0; i < 4; i++) acc[s][nt][i] = 0.0f;

    issue(0);
    issue(1);
    for (int c = 0; c < SK / KC; c++) {      // 16 chunks
        if (c < 15) { CP_WAIT(1); }          // group c complete, c+1 may fly
        else        { CP_WAIT(0); }
        __syncthreads();                     // single barrier per chunk

        const int s3 = c % 3;
        const uint32_t bufA = smb + s3 * ABUF;
        const uint32_t bufB = smb + SB_BASE + s3 * BBUFB;
#pragma unroll
        for (int ks = 0; ks < 4; ks++) {
            const int kb2 = ks * 32;
            uint32_t a0[4], a1[4];
            ldsm4(a0, bufA + aAoff + kb2);
            ldsm4(a1, bufA + aAoff + 16 * PIT + kb2);
            uint32_t bf[4][2];
#pragma unroll
            for (int p = 0; p < 2; p++) {
                uint32_t r4[4];
                ldsm4(r4, bufB + aBoff + p * 16 * PIT + kb2);
                bf[2 * p][0] = r4[0]; bf[2 * p][1] = r4[1];
                bf[2 * p + 1][0] = r4[2]; bf[2 * p + 1][1] = r4[3];
            }
#pragma unroll
            for (int nt = 0; nt < 4; nt++) {
                mma16816h(acc[0][nt], a0, bf[nt]);
                mma16816h(acc[1][nt], a1, bf[nt]);
            }
        }
        if (c + 2 < 16) issue(c + 2);        // reuses compute(c-1)'s buffer
    }

    // epilogue
    const int cb = 2 * (lane & 3);
#pragma unroll
    for (int s = 0; s < 2; s++) {
        const int row0 = m0 + wr * 32 + s * 16 + (lane >> 2);
#pragma unroll
        for (int nt = 0; nt < 4; nt++) {
            int col = (wc * 4 + nt) * 8 + cb;
            *reinterpret_cast<float2*>(out + (size_t)row0 * FF + col) =
                make_float2(acc[s][nt][0], acc[s][nt][1]);
            *reinterpret_cast<float2*>(out + (size_t)(row0 + 8) * FF + col) =
                make_float2(acc[s][nt][2], acc[s][nt][3]);
        }
    }
}

extern "C" void kernel_launch(void* const* d_in, const int* in_sizes, int n_in,
                              void* d_out, int out_size) {
    const float* nodes = (const float*)d_in[0];
    const int*   nlist = (const int*)d_in[1];
    const float* edges = (const float*)d_in[2];
    const float* w     = (const float*)d_in[3];
    float* out = (float*)d_out;
    (void)in_sizes; (void)n_in; (void)out_size;

    cudaFuncSetAttribute(k_stage1,
                         cudaFuncAttributeMaxDynamicSharedMemorySize, S1SMEM);
    cudaFuncSetAttribute(k_stage2,
                         cudaFuncAttributeMaxDynamicSharedMemorySize, SMEM2_SZ);

    k_conv<<<NT * FF / 4 / 256, 256>>>(nodes, w);
    k_stage1<<<NT / S1NODES, 256, S1SMEM>>>(nlist, edges);
    k_stage2<<<NT / 128, 256, SMEM2_SZ>>>(out);
}